// round 3
// baseline (speedup 1.0000x reference)
#include <cuda_runtime.h>

#define BATCH 16
#define NN    10000
#define NE    160000
#define INF   19
#define HD    64
#define OUTF  32
#define BN    (BATCH*NN)
#define LNEPS 1e-5f

// ---------------- scratch (device globals; no allocs allowed) ----------------
__device__ float g_x[(size_t)BN*HD];       // ping
__device__ float g_y[(size_t)BN*HD];       // pong
__device__ int   g_cnt[BN];
__device__ int   g_rowptr[BN];
__device__ int   g_cursor[BN];             // after scatter: row end
__device__ int   g_csr[(size_t)BATCH*NE];
__device__ int   g_is64;

// ---------------- edge dtype detection (int64 vs int32) ----------------
__global__ void detect_kernel(const int* __restrict__ e) {
    int is64 = 1;
    for (int i = 0; i < 128; i++) if (e[2*i+1] != 0) { is64 = 0; break; }
    g_is64 = is64;
}

__device__ __forceinline__ int load_idx(const void* ei, size_t idx, int is64) {
    return is64 ? (int)((const long long*)ei)[idx] : ((const int*)ei)[idx];
}

// ---------------- CSR build ----------------
__global__ void zero_cnt_kernel() {
    int i = blockIdx.x*256 + threadIdx.x;
    if (i < BN) g_cnt[i] = 0;
}

__global__ void hist_kernel(const void* __restrict__ ei) {
    int i = blockIdx.x*256 + threadIdx.x;
    if (i >= BATCH*NE) return;
    int is64 = g_is64;
    int b = i / NE, e = i - b*NE;
    int dst = load_idx(ei, (size_t)b*2*NE + NE + e, is64);
    atomicAdd(&g_cnt[b*NN + dst], 1);
}

__global__ void scan_kernel() {
    __shared__ int s[1024];
    __shared__ int carry;
    int b = blockIdx.x, t = threadIdx.x;
    if (t == 0) carry = 0;
    __syncthreads();
    for (int base = 0; base < NN; base += 1024) {
        int i = base + t;
        int v = (i < NN) ? g_cnt[b*NN + i] : 0;
        s[t] = v;
        __syncthreads();
        #pragma unroll
        for (int off = 1; off < 1024; off <<= 1) {
            int y = (t >= off) ? s[t - off] : 0;
            __syncthreads();
            if (t >= off) s[t] += y;
            __syncthreads();
        }
        int excl = s[t] - v + carry;
        if (i < NN) { g_rowptr[b*NN + i] = excl; g_cursor[b*NN + i] = excl; }
        __syncthreads();
        if (t == 0) carry += s[1023];
        __syncthreads();
    }
}

__global__ void scatter_kernel(const void* __restrict__ ei) {
    int i = blockIdx.x*256 + threadIdx.x;
    if (i >= BATCH*NE) return;
    int is64 = g_is64;
    int b = i / NE, e = i - b*NE;
    int src = load_idx(ei, (size_t)b*2*NE + e,      is64);
    int dst = load_idx(ei, (size_t)b*2*NE + NE + e, is64);
    int pos = atomicAdd(&g_cursor[b*NN + dst], 1);
    g_csr[(size_t)b*NE + pos] = src;
}

// ---------------- helpers ----------------
#define FMA8(acc, a, w0, w1) do { \
    acc[0] += (a)*(w0).x; acc[1] += (a)*(w0).y; acc[2] += (a)*(w0).z; acc[3] += (a)*(w0).w; \
    acc[4] += (a)*(w1).x; acc[5] += (a)*(w1).y; acc[6] += (a)*(w1).z; acc[7] += (a)*(w1).w; } while(0)

// ---------------- encoder: x = relu(nf@W1+b1)@W2+b2 ----------------
__global__ __launch_bounds__(256) void encode_kernel(
    const float* __restrict__ nf,
    const float* __restrict__ W1, const float* __restrict__ b1,
    const float* __restrict__ W2, const float* __restrict__ b2)
{
    __shared__ float sW1[INF*HD];
    __shared__ float sW2[HD*HD];
    __shared__ float sb1[HD], sb2[HD];
    __shared__ float snf[64*20];
    __shared__ float sh[64*68];
    int t = threadIdx.x;
    for (int i = t; i < INF*HD; i += 256) sW1[i] = W1[i];
    for (int i = t; i < HD*HD;  i += 256) sW2[i] = W2[i];
    if (t < HD) { sb1[t] = b1[t]; sb2[t] = b2[t]; }
    int base = blockIdx.x * 64;
    for (int i = t; i < 64*INF; i += 256) {
        int node = i / INF, k = i - node*INF;
        snf[node*20 + k] = nf[(size_t)(base + node)*INF + k];
    }
    __syncthreads();

    int colg = t & 7, pair = t >> 3;
    int c0 = colg << 3;
    int n0 = pair*2, n1 = n0 + 1;

    float acc0[8], acc1[8];
    #pragma unroll
    for (int j = 0; j < 8; j++) { acc0[j] = sb1[c0+j]; acc1[j] = acc0[j]; }
    for (int k = 0; k < INF; k++) {
        float a0 = snf[n0*20 + k], a1 = snf[n1*20 + k];
        float4 w0 = *(const float4*)&sW1[k*HD + c0];
        float4 w1 = *(const float4*)&sW1[k*HD + c0 + 4];
        FMA8(acc0, a0, w0, w1);
        FMA8(acc1, a1, w0, w1);
    }
    #pragma unroll
    for (int j = 0; j < 8; j++) {
        sh[n0*68 + c0 + j] = fmaxf(acc0[j], 0.f);
        sh[n1*68 + c0 + j] = fmaxf(acc1[j], 0.f);
    }
    __syncthreads();

    #pragma unroll
    for (int j = 0; j < 8; j++) { acc0[j] = sb2[c0+j]; acc1[j] = acc0[j]; }
    for (int k = 0; k < HD; k += 4) {
        float4 a0 = *(const float4*)&sh[n0*68 + k];
        float4 a1 = *(const float4*)&sh[n1*68 + k];
        #pragma unroll
        for (int kk = 0; kk < 4; kk++) {
            float av0 = ((const float*)&a0)[kk];
            float av1 = ((const float*)&a1)[kk];
            float4 w0 = *(const float4*)&sW2[(k+kk)*HD + c0];
            float4 w1 = *(const float4*)&sW2[(k+kk)*HD + c0 + 4];
            FMA8(acc0, av0, w0, w1);
            FMA8(acc1, av1, w0, w1);
        }
    }
    float* o0 = g_x + (size_t)(base + n0)*HD + c0;
    float* o1 = g_x + (size_t)(base + n1)*HD + c0;
    *(float4*)(o0)   = make_float4(acc0[0], acc0[1], acc0[2], acc0[3]);
    *(float4*)(o0+4) = make_float4(acc0[4], acc0[5], acc0[6], acc0[7]);
    *(float4*)(o1)   = make_float4(acc1[0], acc1[1], acc1[2], acc1[3]);
    *(float4*)(o1+4) = make_float4(acc1[4], acc1[5], acc1[6], acc1[7]);
}

// ---------------- fused conv layer: gather-mean + concat@W + b + residual + LN + relu ----------------
// dir==0: g_x -> g_y ; dir==1: g_y -> g_x
__global__ __launch_bounds__(256) void conv_kernel(
    int dir,
    const float* __restrict__ W, const float* __restrict__ bias,
    const float* __restrict__ gam, const float* __restrict__ bet)
{
    const float* __restrict__ xin = dir ? g_y : g_x;
    float*       __restrict__ xout = dir ? g_x : g_y;

    extern __shared__ float sm[];
    float* sW    = sm;                 // 128*64 = 8192
    float* scomb = sm + 8192;          // 64*132 = 8448 (x | agg), padded
    float* sb    = scomb + 8448;       // 64
    float* sg    = sb + 64;            // 64
    float* sbe   = sg + 64;            // 64

    int t = threadIdx.x;
    #pragma unroll 4
    for (int i = t; i < 8192; i += 256) sW[i] = W[i];
    if (t < 64) { sb[t] = bias[t]; sg[t] = gam[t]; sbe[t] = bet[t]; }

    // ---- phase A: load self + aggregate neighbors (4 threads per node, 16 feats each)
    {
        int node = t >> 2;
        int f0 = (t & 3) << 4;
        int gn = blockIdx.x*64 + node;
        int b = gn / NN;
        const float4* xr = (const float4*)(xin + (size_t)gn*HD + f0);
        float4 s0 = xr[0], s1 = xr[1], s2 = xr[2], s3 = xr[3];
        float* cp = &scomb[node*132 + f0];
        *(float4*)(cp)    = s0;
        *(float4*)(cp+4)  = s1;
        *(float4*)(cp+8)  = s2;
        *(float4*)(cp+12) = s3;

        int start = g_rowptr[gn], end = g_cursor[gn];
        float4 a0 = make_float4(0,0,0,0), a1 = a0, a2 = a0, a3 = a0;
        const int*   csr = g_csr + (size_t)b*NE;
        const float* xb  = xin + (size_t)b*NN*HD;
        for (int j = start; j < end; j++) {
            int s = csr[j];
            const float4* r = (const float4*)(xb + (size_t)s*HD + f0);
            float4 u0 = r[0], u1 = r[1], u2 = r[2], u3 = r[3];
            a0.x += u0.x; a0.y += u0.y; a0.z += u0.z; a0.w += u0.w;
            a1.x += u1.x; a1.y += u1.y; a1.z += u1.z; a1.w += u1.w;
            a2.x += u2.x; a2.y += u2.y; a2.z += u2.z; a2.w += u2.w;
            a3.x += u3.x; a3.y += u3.y; a3.z += u3.z; a3.w += u3.w;
        }
        float sc = 1.f / fmaxf((float)(end - start), 1.f);
        float* ap = cp + 64;
        *(float4*)(ap)    = make_float4(a0.x*sc, a0.y*sc, a0.z*sc, a0.w*sc);
        *(float4*)(ap+4)  = make_float4(a1.x*sc, a1.y*sc, a1.z*sc, a1.w*sc);
        *(float4*)(ap+8)  = make_float4(a2.x*sc, a2.y*sc, a2.z*sc, a2.w*sc);
        *(float4*)(ap+12) = make_float4(a3.x*sc, a3.y*sc, a3.z*sc, a3.w*sc);
    }
    __syncthreads();

    // ---- phase B: y = combined@W ; epilogue bias+residual+LN+relu (2 nodes x 8 cols per thread)
    int colg = t & 7, pair = t >> 3;
    int c0 = colg << 3;
    int n0 = pair*2, n1 = n0 + 1;
    const float* cb0 = &scomb[n0*132];
    const float* cb1 = &scomb[n1*132];

    float acc0[8] = {0,0,0,0,0,0,0,0};
    float acc1[8] = {0,0,0,0,0,0,0,0};
    for (int k = 0; k < 128; k += 4) {
        float4 a0 = *(const float4*)(cb0 + k);
        float4 a1 = *(const float4*)(cb1 + k);
        #pragma unroll
        for (int kk = 0; kk < 4; kk++) {
            float av0 = ((const float*)&a0)[kk];
            float av1 = ((const float*)&a1)[kk];
            float4 w0 = *(const float4*)&sW[(k+kk)*HD + c0];
            float4 w1 = *(const float4*)&sW[(k+kk)*HD + c0 + 4];
            FMA8(acc0, av0, w0, w1);
            FMA8(acc1, av1, w0, w1);
        }
    }

    float y0[8], y1[8];
    float s0 = 0.f, q0 = 0.f, s1 = 0.f, q1 = 0.f;
    #pragma unroll
    for (int j = 0; j < 8; j++) {
        y0[j] = acc0[j] + sb[c0+j] + cb0[c0+j];   // + bias + residual
        y1[j] = acc1[j] + sb[c0+j] + cb1[c0+j];
        s0 += y0[j]; q0 += y0[j]*y0[j];
        s1 += y1[j]; q1 += y1[j]*y1[j];
    }
    #pragma unroll
    for (int off = 1; off < 8; off <<= 1) {
        s0 += __shfl_xor_sync(0xffffffffu, s0, off, 8);
        q0 += __shfl_xor_sync(0xffffffffu, q0, off, 8);
        s1 += __shfl_xor_sync(0xffffffffu, s1, off, 8);
        q1 += __shfl_xor_sync(0xffffffffu, q1, off, 8);
    }
    const float invH = 1.f/64.f;
    float mu0 = s0*invH, var0 = q0*invH - mu0*mu0;
    float mu1 = s1*invH, var1 = q1*invH - mu1*mu1;
    float iv0 = rsqrtf(var0 + LNEPS);
    float iv1 = rsqrtf(var1 + LNEPS);

    float r0[8], r1[8];
    #pragma unroll
    for (int j = 0; j < 8; j++) {
        r0[j] = fmaxf((y0[j]-mu0)*iv0*sg[c0+j] + sbe[c0+j], 0.f);
        r1[j] = fmaxf((y1[j]-mu1)*iv1*sg[c0+j] + sbe[c0+j], 0.f);
    }
    float* o0 = xout + (size_t)(blockIdx.x*64 + n0)*HD + c0;
    float* o1 = xout + (size_t)(blockIdx.x*64 + n1)*HD + c0;
    *(float4*)(o0)   = make_float4(r0[0], r0[1], r0[2], r0[3]);
    *(float4*)(o0+4) = make_float4(r0[4], r0[5], r0[6], r0[7]);
    *(float4*)(o1)   = make_float4(r1[0], r1[1], r1[2], r1[3]);
    *(float4*)(o1+4) = make_float4(r1[4], r1[5], r1[6], r1[7]);
}

// ---------------- output head: out = x @ out_w + out_b (reads g_y) ----------------
__global__ __launch_bounds__(256) void out_kernel(
    const float* __restrict__ W, const float* __restrict__ bias,
    float* __restrict__ out)
{
    __shared__ float sW[HD*OUTF];
    __shared__ float sx[64*68];
    __shared__ float sb[OUTF];
    const float* __restrict__ xin = g_y;
    int t = threadIdx.x;
    for (int i = t; i < HD*OUTF; i += 256) sW[i] = W[i];
    if (t < OUTF) sb[t] = bias[t];
    {
        int node = t >> 2, f0 = (t & 3) << 4;
        int gn = blockIdx.x*64 + node;
        const float4* xr = (const float4*)(xin + (size_t)gn*HD + f0);
        float* sp = &sx[node*68 + f0];
        *(float4*)(sp)    = xr[0];
        *(float4*)(sp+4)  = xr[1];
        *(float4*)(sp+8)  = xr[2];
        *(float4*)(sp+12) = xr[3];
    }
    __syncthreads();

    int colg = t & 7, pair = t >> 3;
    int c0 = colg << 2;
    int n0 = pair*2, n1 = n0 + 1;
    const float* x0 = &sx[n0*68];
    const float* x1 = &sx[n1*68];
    float acc0[4] = {0,0,0,0}, acc1[4] = {0,0,0,0};
    for (int k = 0; k < HD; k += 4) {
        float4 a0 = *(const float4*)(x0 + k);
        float4 a1 = *(const float4*)(x1 + k);
        #pragma unroll
        for (int kk = 0; kk < 4; kk++) {
            float av0 = ((const float*)&a0)[kk];
            float av1 = ((const float*)&a1)[kk];
            float4 w = *(const float4*)&sW[(k+kk)*OUTF + c0];
            acc0[0] += av0*w.x; acc0[1] += av0*w.y; acc0[2] += av0*w.z; acc0[3] += av0*w.w;
            acc1[0] += av1*w.x; acc1[1] += av1*w.y; acc1[2] += av1*w.z; acc1[3] += av1*w.w;
        }
    }
    float4 o0 = make_float4(acc0[0]+sb[c0], acc0[1]+sb[c0+1], acc0[2]+sb[c0+2], acc0[3]+sb[c0+3]);
    float4 o1 = make_float4(acc1[0]+sb[c0], acc1[1]+sb[c0+1], acc1[2]+sb[c0+2], acc1[3]+sb[c0+3]);
    *(float4*)(out + (size_t)(blockIdx.x*64 + n0)*OUTF + c0) = o0;
    *(float4*)(out + (size_t)(blockIdx.x*64 + n1)*OUTF + c0) = o1;
}

// ---------------- launch ----------------
extern "C" void kernel_launch(void* const* d_in, const int* in_sizes, int n_in,
                              void* d_out, int out_size) {
    const float* nf     = (const float*)d_in[0];
    const void*  ei     = d_in[1];
    // d_in[2] = batch_size (unused; shapes fixed)
    const float* enc_w1 = (const float*)d_in[3];
    const float* enc_b1 = (const float*)d_in[4];
    const float* enc_w2 = (const float*)d_in[5];
    const float* enc_b2 = (const float*)d_in[6];
    const float* conv_w = (const float*)d_in[7];
    const float* conv_b = (const float*)d_in[8];
    const float* ln_g   = (const float*)d_in[9];
    const float* ln_b   = (const float*)d_in[10];
    const float* out_w  = (const float*)d_in[11];
    const float* out_b  = (const float*)d_in[12];
    float* out = (float*)d_out;

    detect_kernel<<<1, 1>>>((const int*)ei);
    zero_cnt_kernel<<<(BN + 255)/256, 256>>>();
    int eb = (BATCH*NE + 255)/256;
    hist_kernel<<<eb, 256>>>(ei);
    scan_kernel<<<BATCH, 1024>>>();
    scatter_kernel<<<eb, 256>>>(ei);

    encode_kernel<<<BN/64, 256>>>(nf, enc_w1, enc_b1, enc_w2, enc_b2);

    int convsmem = (8192 + 8448 + 192) * (int)sizeof(float);   // 67328 B
    cudaFuncSetAttribute(conv_kernel, cudaFuncAttributeMaxDynamicSharedMemorySize, convsmem);
    for (int l = 0; l < 3; l++) {
        conv_kernel<<<BN/64, 256, convsmem>>>(l & 1,
            conv_w + (size_t)l*128*64, conv_b + (size_t)l*64,
            ln_g + (size_t)l*64, ln_b + (size_t)l*64);
    }
    // after L0: g_y, L1: g_x, L2: g_y -> out reads g_y
    out_kernel<<<BN/64, 256>>>(out_w, out_b, out);
}

// round 4
// speedup vs baseline: 1.0524x; 1.0524x over previous
#include <cuda_runtime.h>

#define BATCH 16
#define NN    10000
#define NE    160000
#define INF   19
#define HD    64
#define OUTF  32
#define BN    (BATCH*NN)
#define LNEPS 1e-5f

typedef unsigned long long u64;

// ---------------- scratch (device globals; no allocs allowed) ----------------
__device__ float g_x[(size_t)BN*HD];       // ping
__device__ float g_y[(size_t)BN*HD];       // pong
__device__ int   g_cnt[BN];
__device__ int   g_rowptr[BN];
__device__ int   g_cursor[BN];             // after scatter: row end
__device__ int   g_csr[(size_t)BATCH*NE];
__device__ int   g_is64;

// ---------------- packed f32x2 helpers (FFMA2 path, PTX-only) ----------------
__device__ __forceinline__ u64 pk(float x) {
    u64 r; asm("mov.b64 %0,{%1,%1};" : "=l"(r) : "f"(x)); return r;
}
__device__ __forceinline__ void fma2(u64& d, u64 a, u64 b) {
    asm("fma.rn.f32x2 %0,%1,%2,%0;" : "+l"(d) : "l"(a), "l"(b));
}
__device__ __forceinline__ void add2(u64& d, u64 a) {
    asm("add.rn.f32x2 %0,%0,%1;" : "+l"(d) : "l"(a));
}
__device__ __forceinline__ void mul2(u64& d, u64 a) {
    asm("mul.rn.f32x2 %0,%0,%1;" : "+l"(d) : "l"(a));
}
__device__ __forceinline__ void upk(u64 v, float& lo, float& hi) {
    asm("mov.b64 {%0,%1},%2;" : "=f"(lo), "=f"(hi) : "l"(v));
}

// ---------------- edge dtype detection (int64 vs int32), one warp ----------------
__global__ void detect_kernel(const int* __restrict__ e) {
    int t = threadIdx.x;
    int nz = 0;
    #pragma unroll
    for (int i = t; i < 128; i += 32) nz |= e[2*i + 1];
    unsigned any = __ballot_sync(0xffffffffu, nz != 0);
    if (t == 0) g_is64 = (any == 0) ? 1 : 0;
}

__device__ __forceinline__ int load_idx(const void* ei, size_t idx, int is64) {
    return is64 ? (int)((const long long*)ei)[idx] : ((const int*)ei)[idx];
}

// ---------------- CSR build ----------------
__global__ void zero_cnt_kernel() {
    int i = blockIdx.x*256 + threadIdx.x;
    if (i < BN) g_cnt[i] = 0;
}

__global__ void hist_kernel(const void* __restrict__ ei) {
    int i = blockIdx.x*256 + threadIdx.x;
    if (i >= BATCH*NE) return;
    int is64 = g_is64;
    int b = i / NE, e = i - b*NE;
    int dst = load_idx(ei, (size_t)b*2*NE + NE + e, is64);
    atomicAdd(&g_cnt[b*NN + dst], 1);
}

// shfl-based scan: 16 blocks x 1024, 10 chunks each, 4 syncs/chunk
__global__ void scan_kernel() {
    __shared__ int wsum[32];
    __shared__ int carry;
    int b = blockIdx.x, t = threadIdx.x, lane = t & 31, w = t >> 5;
    if (t == 0) carry = 0;
    __syncthreads();
    for (int base = 0; base < NN; base += 1024) {
        int i = base + t;
        int v = (i < NN) ? g_cnt[b*NN + i] : 0;
        int x = v;
        #pragma unroll
        for (int o = 1; o < 32; o <<= 1) {
            int y = __shfl_up_sync(0xffffffffu, x, o);
            if (lane >= o) x += y;
        }
        if (lane == 31) wsum[w] = x;
        __syncthreads();
        if (w == 0) {
            int s = wsum[lane];
            #pragma unroll
            for (int o = 1; o < 32; o <<= 1) {
                int y = __shfl_up_sync(0xffffffffu, s, o);
                if (lane >= o) s += y;
            }
            wsum[lane] = s;
        }
        __syncthreads();
        int excl = carry + (w ? wsum[w-1] : 0) + x - v;
        if (i < NN) { g_rowptr[b*NN + i] = excl; g_cursor[b*NN + i] = excl; }
        __syncthreads();
        if (t == 0) carry += wsum[31];
        __syncthreads();
    }
}

__global__ void scatter_kernel(const void* __restrict__ ei) {
    int i = blockIdx.x*256 + threadIdx.x;
    if (i >= BATCH*NE) return;
    int is64 = g_is64;
    int b = i / NE, e = i - b*NE;
    int src = load_idx(ei, (size_t)b*2*NE + e,      is64);
    int dst = load_idx(ei, (size_t)b*2*NE + NE + e, is64);
    int pos = atomicAdd(&g_cursor[b*NN + dst], 1);
    g_csr[(size_t)b*NE + pos] = src;
}

// ---------------- encoder: x = relu(nf@W1+b1)@W2+b2 (f32x2 GEMMs) ----------------
__global__ __launch_bounds__(256) void encode_kernel(
    const float* __restrict__ nf,
    const float* __restrict__ W1, const float* __restrict__ b1,
    const float* __restrict__ W2, const float* __restrict__ b2)
{
    __shared__ float sW1[INF*HD];
    __shared__ float sW2[HD*HD];
    __shared__ float sb1[HD], sb2[HD];
    __shared__ float snf[64*20];
    __shared__ float sh[64*68];
    int t = threadIdx.x;
    for (int i = t; i < INF*HD; i += 256) sW1[i] = W1[i];
    for (int i = t; i < HD*HD;  i += 256) sW2[i] = W2[i];
    if (t < HD) { sb1[t] = b1[t]; sb2[t] = b2[t]; }
    int base = blockIdx.x * 64;
    for (int i = t; i < 64*INF; i += 256) {
        int node = i / INF, k = i - node*INF;
        snf[node*20 + k] = nf[(size_t)(base + node)*INF + k];
    }
    __syncthreads();

    int colg = t & 7, pair = t >> 3;
    int c0 = colg << 3;
    int n0 = pair*2, n1 = n0 + 1;

    // GEMM1: 19 -> 64, relu
    u64 p0[4] = {0,0,0,0}, p1[4] = {0,0,0,0};
    for (int k = 0; k < INF; k++) {
        u64 A0 = pk(snf[n0*20 + k]), A1 = pk(snf[n1*20 + k]);
        const ulonglong2* wp = (const ulonglong2*)&sW1[k*HD + c0];
        ulonglong2 wa = wp[0], wb = wp[1];
        fma2(p0[0], A0, wa.x); fma2(p0[1], A0, wa.y); fma2(p0[2], A0, wb.x); fma2(p0[3], A0, wb.y);
        fma2(p1[0], A1, wa.x); fma2(p1[1], A1, wa.y); fma2(p1[2], A1, wb.x); fma2(p1[3], A1, wb.y);
    }
    float h0[8], h1[8];
    #pragma unroll
    for (int j = 0; j < 4; j++) { upk(p0[j], h0[2*j], h0[2*j+1]); upk(p1[j], h1[2*j], h1[2*j+1]); }
    #pragma unroll
    for (int j = 0; j < 8; j++) {
        sh[n0*68 + c0 + j] = fmaxf(h0[j] + sb1[c0+j], 0.f);
        sh[n1*68 + c0 + j] = fmaxf(h1[j] + sb1[c0+j], 0.f);
    }
    __syncthreads();

    // GEMM2: 64 -> 64
    #pragma unroll
    for (int j = 0; j < 4; j++) { p0[j] = 0; p1[j] = 0; }
    for (int k = 0; k < HD; k += 4) {
        float4 a0 = *(const float4*)&sh[n0*68 + k];
        float4 a1 = *(const float4*)&sh[n1*68 + k];
        #pragma unroll
        for (int kk = 0; kk < 4; kk++) {
            u64 A0 = pk(((const float*)&a0)[kk]);
            u64 A1 = pk(((const float*)&a1)[kk]);
            const ulonglong2* wp = (const ulonglong2*)&sW2[(k+kk)*HD + c0];
            ulonglong2 wa = wp[0], wb = wp[1];
            fma2(p0[0], A0, wa.x); fma2(p0[1], A0, wa.y); fma2(p0[2], A0, wb.x); fma2(p0[3], A0, wb.y);
            fma2(p1[0], A1, wa.x); fma2(p1[1], A1, wa.y); fma2(p1[2], A1, wb.x); fma2(p1[3], A1, wb.y);
        }
    }
    float y0[8], y1[8];
    #pragma unroll
    for (int j = 0; j < 4; j++) { upk(p0[j], y0[2*j], y0[2*j+1]); upk(p1[j], y1[2*j], y1[2*j+1]); }
    float* o0 = g_x + (size_t)(base + n0)*HD + c0;
    float* o1 = g_x + (size_t)(base + n1)*HD + c0;
    *(float4*)(o0)   = make_float4(y0[0]+sb2[c0+0], y0[1]+sb2[c0+1], y0[2]+sb2[c0+2], y0[3]+sb2[c0+3]);
    *(float4*)(o0+4) = make_float4(y0[4]+sb2[c0+4], y0[5]+sb2[c0+5], y0[6]+sb2[c0+6], y0[7]+sb2[c0+7]);
    *(float4*)(o1)   = make_float4(y1[0]+sb2[c0+0], y1[1]+sb2[c0+1], y1[2]+sb2[c0+2], y1[3]+sb2[c0+3]);
    *(float4*)(o1+4) = make_float4(y1[4]+sb2[c0+4], y1[5]+sb2[c0+5], y1[6]+sb2[c0+6], y1[7]+sb2[c0+7]);
}

// ---------------- fused conv layer (+ optional fused output head) ----------------
// dir==0: g_x -> g_y ; dir==1: g_y -> g_x.  If outp != null: last layer, write head output only.
__global__ __launch_bounds__(256) void conv_kernel(
    int dir,
    const float* __restrict__ W, const float* __restrict__ bias,
    const float* __restrict__ gam, const float* __restrict__ bet,
    const float* __restrict__ Wo, const float* __restrict__ bo,
    float* __restrict__ outp)
{
    const float* __restrict__ xin  = dir ? g_y : g_x;
    float*       __restrict__ xout = dir ? g_x : g_y;

    extern __shared__ float sm[];
    float* sW    = sm;                 // 128*64 = 8192
    float* scomb = sm + 8192;          // 64*132 = 8448 (x | agg)
    float* sb    = scomb + 8448;       // 64
    float* sg    = sb + 64;            // 64
    float* sbe   = sg + 64;            // 64
    float* sWo   = sbe + 64;           // 64*32 = 2048
    float* sbo   = sWo + 2048;         // 32

    int t = threadIdx.x;
    #pragma unroll 4
    for (int i = t; i < 8192; i += 256) sW[i] = W[i];
    if (t < 64) { sb[t] = bias[t]; sg[t] = gam[t]; sbe[t] = bet[t]; }
    if (outp) {
        for (int i = t; i < HD*OUTF; i += 256) sWo[i] = Wo[i];
        if (t < OUTF) sbo[t] = bo[t];
    }

    // ---- phase A: self + mean-aggregate (4 threads/node, 16 feats each, unroll-2)
    {
        int node = t >> 2;
        int f0 = (t & 3) << 4;
        int gn = blockIdx.x*64 + node;
        int b = gn / NN;
        const ulonglong2* xr = (const ulonglong2*)(xin + (size_t)gn*HD + f0);
        ulonglong2 s0 = xr[0], s1 = xr[1], s2 = xr[2], s3 = xr[3];
        float* cp = &scomb[node*132 + f0];
        *(ulonglong2*)(cp)    = s0;
        *(ulonglong2*)(cp+4)  = s1;
        *(ulonglong2*)(cp+8)  = s2;
        *(ulonglong2*)(cp+12) = s3;

        int start = g_rowptr[gn], end = g_cursor[gn];
        u64 acc[8] = {0,0,0,0,0,0,0,0};
        const int*   csr = g_csr + (size_t)b*NE;
        const float* xb  = xin + (size_t)b*NN*HD;
        int j = start;
        for (; j + 2 <= end; j += 2) {
            int sA = csr[j], sB = csr[j+1];
            const ulonglong2* rA = (const ulonglong2*)(xb + (size_t)sA*HD + f0);
            const ulonglong2* rB = (const ulonglong2*)(xb + (size_t)sB*HD + f0);
            ulonglong2 uA0 = rA[0], uA1 = rA[1], uA2 = rA[2], uA3 = rA[3];
            ulonglong2 uB0 = rB[0], uB1 = rB[1], uB2 = rB[2], uB3 = rB[3];
            add2(acc[0], uA0.x); add2(acc[1], uA0.y);
            add2(acc[2], uA1.x); add2(acc[3], uA1.y);
            add2(acc[4], uA2.x); add2(acc[5], uA2.y);
            add2(acc[6], uA3.x); add2(acc[7], uA3.y);
            add2(acc[0], uB0.x); add2(acc[1], uB0.y);
            add2(acc[2], uB1.x); add2(acc[3], uB1.y);
            add2(acc[4], uB2.x); add2(acc[5], uB2.y);
            add2(acc[6], uB3.x); add2(acc[7], uB3.y);
        }
        if (j < end) {
            int sA = csr[j];
            const ulonglong2* rA = (const ulonglong2*)(xb + (size_t)sA*HD + f0);
            ulonglong2 uA0 = rA[0], uA1 = rA[1], uA2 = rA[2], uA3 = rA[3];
            add2(acc[0], uA0.x); add2(acc[1], uA0.y);
            add2(acc[2], uA1.x); add2(acc[3], uA1.y);
            add2(acc[4], uA2.x); add2(acc[5], uA2.y);
            add2(acc[6], uA3.x); add2(acc[7], uA3.y);
        }
        u64 SC = pk(1.f / fmaxf((float)(end - start), 1.f));
        #pragma unroll
        for (int q = 0; q < 8; q++) mul2(acc[q], SC);
        float* ap = cp + 64;
        *(ulonglong2*)(ap)    = make_ulonglong2(acc[0], acc[1]);
        *(ulonglong2*)(ap+4)  = make_ulonglong2(acc[2], acc[3]);
        *(ulonglong2*)(ap+8)  = make_ulonglong2(acc[4], acc[5]);
        *(ulonglong2*)(ap+12) = make_ulonglong2(acc[6], acc[7]);
    }
    __syncthreads();

    // ---- phase B: y = combined@W (f32x2); epilogue bias+residual+LN+relu
    int colg = t & 7, pair = t >> 3;
    int c0 = colg << 3;
    int n0 = pair*2, n1 = n0 + 1;
    const float* cb0 = &scomb[n0*132];
    const float* cb1 = &scomb[n1*132];

    u64 p0[4] = {0,0,0,0}, p1[4] = {0,0,0,0};
    for (int k = 0; k < 128; k += 4) {
        float4 a0 = *(const float4*)(cb0 + k);
        float4 a1 = *(const float4*)(cb1 + k);
        #pragma unroll
        for (int kk = 0; kk < 4; kk++) {
            u64 A0 = pk(((const float*)&a0)[kk]);
            u64 A1 = pk(((const float*)&a1)[kk]);
            const ulonglong2* wp = (const ulonglong2*)&sW[(k+kk)*HD + c0];
            ulonglong2 wa = wp[0], wb = wp[1];
            fma2(p0[0], A0, wa.x); fma2(p0[1], A0, wa.y); fma2(p0[2], A0, wb.x); fma2(p0[3], A0, wb.y);
            fma2(p1[0], A1, wa.x); fma2(p1[1], A1, wa.y); fma2(p1[2], A1, wb.x); fma2(p1[3], A1, wb.y);
        }
    }

    float y0[8], y1[8];
    #pragma unroll
    for (int j = 0; j < 4; j++) { upk(p0[j], y0[2*j], y0[2*j+1]); upk(p1[j], y1[2*j], y1[2*j+1]); }
    float s0 = 0.f, q0 = 0.f, s1 = 0.f, q1 = 0.f;
    #pragma unroll
    for (int j = 0; j < 8; j++) {
        y0[j] += sb[c0+j] + cb0[c0+j];
        y1[j] += sb[c0+j] + cb1[c0+j];
        s0 += y0[j]; q0 += y0[j]*y0[j];
        s1 += y1[j]; q1 += y1[j]*y1[j];
    }
    #pragma unroll
    for (int off = 1; off < 8; off <<= 1) {
        s0 += __shfl_xor_sync(0xffffffffu, s0, off, 8);
        q0 += __shfl_xor_sync(0xffffffffu, q0, off, 8);
        s1 += __shfl_xor_sync(0xffffffffu, s1, off, 8);
        q1 += __shfl_xor_sync(0xffffffffu, q1, off, 8);
    }
    const float invH = 1.f/64.f;
    float mu0 = s0*invH, var0 = q0*invH - mu0*mu0;
    float mu1 = s1*invH, var1 = q1*invH - mu1*mu1;
    float iv0 = rsqrtf(var0 + LNEPS);
    float iv1 = rsqrtf(var1 + LNEPS);

    float r0[8], r1[8];
    #pragma unroll
    for (int j = 0; j < 8; j++) {
        r0[j] = fmaxf((y0[j]-mu0)*iv0*sg[c0+j] + sbe[c0+j], 0.f);
        r1[j] = fmaxf((y1[j]-mu1)*iv1*sg[c0+j] + sbe[c0+j], 0.f);
    }

    if (!outp) {
        float* o0 = xout + (size_t)(blockIdx.x*64 + n0)*HD + c0;
        float* o1 = xout + (size_t)(blockIdx.x*64 + n1)*HD + c0;
        *(float4*)(o0)   = make_float4(r0[0], r0[1], r0[2], r0[3]);
        *(float4*)(o0+4) = make_float4(r0[4], r0[5], r0[6], r0[7]);
        *(float4*)(o1)   = make_float4(r1[0], r1[1], r1[2], r1[3]);
        *(float4*)(o1+4) = make_float4(r1[4], r1[5], r1[6], r1[7]);
        return;
    }

    // ---- fused output head: out = r @ Wo + bo
    __syncthreads();                       // everyone done reading scomb
    {
        float* w0p = &scomb[n0*132 + c0];
        float* w1p = &scomb[n1*132 + c0];
        *(float4*)(w0p)   = make_float4(r0[0], r0[1], r0[2], r0[3]);
        *(float4*)(w0p+4) = make_float4(r0[4], r0[5], r0[6], r0[7]);
        *(float4*)(w1p)   = make_float4(r1[0], r1[1], r1[2], r1[3]);
        *(float4*)(w1p+4) = make_float4(r1[4], r1[5], r1[6], r1[7]);
    }
    __syncthreads();

    int c4 = colg << 2;                    // 4 output cols per thread
    u64 q0p[2] = {0,0}, q1p[2] = {0,0};
    const float* x0 = &scomb[n0*132];
    const float* x1 = &scomb[n1*132];
    for (int k = 0; k < HD; k += 4) {
        float4 a0 = *(const float4*)(x0 + k);
        float4 a1 = *(const float4*)(x1 + k);
        #pragma unroll
        for (int kk = 0; kk < 4; kk++) {
            u64 A0 = pk(((const float*)&a0)[kk]);
            u64 A1 = pk(((const float*)&a1)[kk]);
            ulonglong2 w = *(const ulonglong2*)&sWo[(k+kk)*OUTF + c4];
            fma2(q0p[0], A0, w.x); fma2(q0p[1], A0, w.y);
            fma2(q1p[0], A1, w.x); fma2(q1p[1], A1, w.y);
        }
    }
    float z0[4], z1[4];
    upk(q0p[0], z0[0], z0[1]); upk(q0p[1], z0[2], z0[3]);
    upk(q1p[0], z1[0], z1[1]); upk(q1p[1], z1[2], z1[3]);
    float4 o0 = make_float4(z0[0]+sbo[c4], z0[1]+sbo[c4+1], z0[2]+sbo[c4+2], z0[3]+sbo[c4+3]);
    float4 o1 = make_float4(z1[0]+sbo[c4], z1[1]+sbo[c4+1], z1[2]+sbo[c4+2], z1[3]+sbo[c4+3]);
    *(float4*)(outp + (size_t)(blockIdx.x*64 + n0)*OUTF + c4) = o0;
    *(float4*)(outp + (size_t)(blockIdx.x*64 + n1)*OUTF + c4) = o1;
}

// ---------------- launch ----------------
extern "C" void kernel_launch(void* const* d_in, const int* in_sizes, int n_in,
                              void* d_out, int out_size) {
    const float* nf     = (const float*)d_in[0];
    const void*  ei     = d_in[1];
    const float* enc_w1 = (const float*)d_in[3];
    const float* enc_b1 = (const float*)d_in[4];
    const float* enc_w2 = (const float*)d_in[5];
    const float* enc_b2 = (const float*)d_in[6];
    const float* conv_w = (const float*)d_in[7];
    const float* conv_b = (const float*)d_in[8];
    const float* ln_g   = (const float*)d_in[9];
    const float* ln_b   = (const float*)d_in[10];
    const float* out_w  = (const float*)d_in[11];
    const float* out_b  = (const float*)d_in[12];
    float* out = (float*)d_out;

    detect_kernel<<<1, 32>>>((const int*)ei);
    zero_cnt_kernel<<<(BN + 255)/256, 256>>>();
    int eb = (BATCH*NE + 255)/256;
    hist_kernel<<<eb, 256>>>(ei);
    scan_kernel<<<BATCH, 1024>>>();
    scatter_kernel<<<eb, 256>>>(ei);

    encode_kernel<<<BN/64, 256>>>(nf, enc_w1, enc_b1, enc_w2, enc_b2);

    int convsmem = (8192 + 8448 + 192 + 2048 + 32) * (int)sizeof(float);   // 75648 B
    cudaFuncSetAttribute(conv_kernel, cudaFuncAttributeMaxDynamicSharedMemorySize, convsmem);
    for (int l = 0; l < 3; l++) {
        conv_kernel<<<BN/64, 256, convsmem>>>(l & 1,
            conv_w + (size_t)l*128*64, conv_b + (size_t)l*64,
            ln_g + (size_t)l*64, ln_b + (size_t)l*64,
            out_w, out_b, (l == 2) ? out : nullptr);
    }
}

// round 5
// speedup vs baseline: 1.1768x; 1.1182x over previous
#include <cuda_runtime.h>
#include <cuda_fp16.h>

#define BATCH 16
#define NN    10000
#define NE    160000
#define INF   19
#define HD    64
#define OUTF  32
#define BN    (BATCH*NN)
#define LNEPS 1e-5f

typedef unsigned long long u64;

// ---------------- scratch (device globals; no allocs allowed) ----------------
__device__ float g_x[(size_t)BN*HD];          // ping (fp32)
__device__ float g_y[(size_t)BN*HD];          // pong (fp32)
__device__ uint4 g_xh[(size_t)BN*8];          // ping (fp16 mirror, 128B/row)
__device__ uint4 g_yh[(size_t)BN*8];          // pong (fp16 mirror)
__device__ __align__(16) int g_cnt[BN];
__device__ __align__(16) int g_rowptr[BN];
__device__ __align__(16) int g_cursor[BN];
__device__ int   g_csr[(size_t)BATCH*NE];
__device__ int   g_is64;

// ---------------- packed f32x2 helpers ----------------
__device__ __forceinline__ u64 pk(float x) {
    u64 r; asm("mov.b64 %0,{%1,%1};" : "=l"(r) : "f"(x)); return r;
}
__device__ __forceinline__ void fma2(u64& d, u64 a, u64 b) {
    asm("fma.rn.f32x2 %0,%1,%2,%0;" : "+l"(d) : "l"(a), "l"(b));
}
__device__ __forceinline__ void add2(u64& d, u64 a) {
    asm("add.rn.f32x2 %0,%0,%1;" : "+l"(d) : "l"(a));
}
__device__ __forceinline__ void mul2(u64& d, u64 a) {
    asm("mul.rn.f32x2 %0,%0,%1;" : "+l"(d) : "l"(a));
}
__device__ __forceinline__ void upk(u64 v, float& lo, float& hi) {
    asm("mov.b64 {%0,%1},%2;" : "=f"(lo), "=f"(hi) : "l"(v));
}
// half2 (as u32) -> f32x2 accumulate
__device__ __forceinline__ void addh2(u64& acc, unsigned h) {
    __half2 hh = *(__half2*)&h;
    float2 f = __half22float2(hh);
    u64 p; asm("mov.b64 %0,{%1,%2};" : "=l"(p) : "f"(f.x), "f"(f.y));
    add2(acc, p);
}
__device__ __forceinline__ void acc16(u64* acc, uint4 A, uint4 B) {
    addh2(acc[0], A.x); addh2(acc[1], A.y); addh2(acc[2], A.z); addh2(acc[3], A.w);
    addh2(acc[4], B.x); addh2(acc[5], B.y); addh2(acc[6], B.z); addh2(acc[7], B.w);
}
__device__ __forceinline__ unsigned f2h2(float a, float b) {
    __half2 h = __floats2half2_rn(a, b);
    return *(unsigned*)&h;
}

// ---------------- detect (block0 warp0) + zero counters, fused ----------------
__global__ void detect_zero_kernel(const int* __restrict__ e) {
    int i = blockIdx.x*256 + threadIdx.x;
    if (i < BN) g_cnt[i] = 0;
    if (blockIdx.x == 0 && threadIdx.x < 32) {
        int nz = 0;
        #pragma unroll
        for (int k = threadIdx.x; k < 128; k += 32) nz |= e[2*k + 1];
        unsigned any = __ballot_sync(0xffffffffu, nz != 0);
        if (threadIdx.x == 0) g_is64 = (any == 0) ? 1 : 0;
    }
}

__device__ __forceinline__ int load_idx(const void* ei, size_t idx, int is64) {
    return is64 ? (int)((const long long*)ei)[idx] : ((const int*)ei)[idx];
}

__global__ void hist_kernel(const void* __restrict__ ei) {
    int i = blockIdx.x*256 + threadIdx.x;
    if (i >= BATCH*NE) return;
    int is64 = g_is64;
    int b = i / NE, e = i - b*NE;
    int dst = load_idx(ei, (size_t)b*2*NE + NE + e, is64);
    atomicAdd(&g_cnt[b*NN + dst], 1);
}

// int4 scan: 2500 int4 per batch, 3 chunks of 1024, register carry
__global__ void scan_kernel() {
    __shared__ int wsum[32];
    int b = blockIdx.x, t = threadIdx.x, lane = t & 31, w = t >> 5;
    const int4* c4 = (const int4*)(g_cnt + b*NN);
    int4* r4 = (int4*)(g_rowptr + b*NN);
    int4* u4 = (int4*)(g_cursor + b*NN);
    int carry = 0;
    for (int base = 0; base < 2500; base += 1024) {
        int i = base + t;
        int4 v = (i < 2500) ? c4[i] : make_int4(0,0,0,0);
        int t1 = v.x, t2 = t1 + v.y, t3 = t2 + v.z, t4 = t3 + v.w;
        int x = t4;
        #pragma unroll
        for (int o = 1; o < 32; o <<= 1) {
            int y = __shfl_up_sync(0xffffffffu, x, o);
            if (lane >= o) x += y;
        }
        if (lane == 31) wsum[w] = x;
        __syncthreads();
        if (w == 0) {
            int s = wsum[lane];
            #pragma unroll
            for (int o = 1; o < 32; o <<= 1) {
                int y = __shfl_up_sync(0xffffffffu, s, o);
                if (lane >= o) s += y;
            }
            wsum[lane] = s;
        }
        __syncthreads();
        int excl = carry + (w ? wsum[w-1] : 0) + x - t4;
        if (i < 2500) {
            int4 rp = make_int4(excl, excl + t1, excl + t2, excl + t3);
            r4[i] = rp; u4[i] = rp;
        }
        carry += wsum[31];
        __syncthreads();
    }
}

__global__ void scatter_kernel(const void* __restrict__ ei) {
    int i = blockIdx.x*256 + threadIdx.x;
    if (i >= BATCH*NE) return;
    int is64 = g_is64;
    int b = i / NE, e = i - b*NE;
    int src = load_idx(ei, (size_t)b*2*NE + e,      is64);
    int dst = load_idx(ei, (size_t)b*2*NE + NE + e, is64);
    int pos = atomicAdd(&g_cursor[b*NN + dst], 1);
    g_csr[b*NE + pos] = src;
}

// ---------------- encoder: x = relu(nf@W1+b1)@W2+b2; writes fp32 + fp16 mirror ----------------
__global__ __launch_bounds__(256) void encode_kernel(
    const float* __restrict__ nf,
    const float* __restrict__ W1, const float* __restrict__ b1,
    const float* __restrict__ W2, const float* __restrict__ b2)
{
    __shared__ float sW1[INF*HD];
    __shared__ float sW2[HD*HD];
    __shared__ float sb1[HD], sb2[HD];
    __shared__ float snf[64*20];
    __shared__ float sh[64*68];
    int t = threadIdx.x;
    for (int i = t; i < INF*HD; i += 256) sW1[i] = W1[i];
    for (int i = t; i < HD*HD;  i += 256) sW2[i] = W2[i];
    if (t < HD) { sb1[t] = b1[t]; sb2[t] = b2[t]; }
    int base = blockIdx.x * 64;
    for (int i = t; i < 64*INF; i += 256) {
        int node = i / INF, k = i - node*INF;
        snf[node*20 + k] = nf[(size_t)(base + node)*INF + k];
    }
    __syncthreads();

    int colg = t & 7, pair = t >> 3;
    int c0 = colg << 3;
    int n0 = pair*2, n1 = n0 + 1;

    u64 p0[4] = {0,0,0,0}, p1[4] = {0,0,0,0};
    for (int k = 0; k < INF; k++) {
        u64 A0 = pk(snf[n0*20 + k]), A1 = pk(snf[n1*20 + k]);
        const ulonglong2* wp = (const ulonglong2*)&sW1[k*HD + c0];
        ulonglong2 wa = wp[0], wb = wp[1];
        fma2(p0[0], A0, wa.x); fma2(p0[1], A0, wa.y); fma2(p0[2], A0, wb.x); fma2(p0[3], A0, wb.y);
        fma2(p1[0], A1, wa.x); fma2(p1[1], A1, wa.y); fma2(p1[2], A1, wb.x); fma2(p1[3], A1, wb.y);
    }
    float h0[8], h1[8];
    #pragma unroll
    for (int j = 0; j < 4; j++) { upk(p0[j], h0[2*j], h0[2*j+1]); upk(p1[j], h1[2*j], h1[2*j+1]); }
    #pragma unroll
    for (int j = 0; j < 8; j++) {
        sh[n0*68 + c0 + j] = fmaxf(h0[j] + sb1[c0+j], 0.f);
        sh[n1*68 + c0 + j] = fmaxf(h1[j] + sb1[c0+j], 0.f);
    }
    __syncthreads();

    #pragma unroll
    for (int j = 0; j < 4; j++) { p0[j] = 0; p1[j] = 0; }
    for (int k = 0; k < HD; k += 4) {
        float4 a0 = *(const float4*)&sh[n0*68 + k];
        float4 a1 = *(const float4*)&sh[n1*68 + k];
        #pragma unroll
        for (int kk = 0; kk < 4; kk++) {
            u64 A0 = pk(((const float*)&a0)[kk]);
            u64 A1 = pk(((const float*)&a1)[kk]);
            const ulonglong2* wp = (const ulonglong2*)&sW2[(k+kk)*HD + c0];
            ulonglong2 wa = wp[0], wb = wp[1];
            fma2(p0[0], A0, wa.x); fma2(p0[1], A0, wa.y); fma2(p0[2], A0, wb.x); fma2(p0[3], A0, wb.y);
            fma2(p1[0], A1, wa.x); fma2(p1[1], A1, wa.y); fma2(p1[2], A1, wb.x); fma2(p1[3], A1, wb.y);
        }
    }
    float y0[8], y1[8];
    #pragma unroll
    for (int j = 0; j < 4; j++) { upk(p0[j], y0[2*j], y0[2*j+1]); upk(p1[j], y1[2*j], y1[2*j+1]); }
    #pragma unroll
    for (int j = 0; j < 8; j++) { y0[j] += sb2[c0+j]; y1[j] += sb2[c0+j]; }

    size_t gn0 = base + n0, gn1 = base + n1;
    float* o0 = g_x + gn0*HD + c0;
    float* o1 = g_x + gn1*HD + c0;
    *(float4*)(o0)   = make_float4(y0[0], y0[1], y0[2], y0[3]);
    *(float4*)(o0+4) = make_float4(y0[4], y0[5], y0[6], y0[7]);
    *(float4*)(o1)   = make_float4(y1[0], y1[1], y1[2], y1[3]);
    *(float4*)(o1+4) = make_float4(y1[4], y1[5], y1[6], y1[7]);
    g_xh[gn0*8 + (c0>>3)] = make_uint4(f2h2(y0[0],y0[1]), f2h2(y0[2],y0[3]), f2h2(y0[4],y0[5]), f2h2(y0[6],y0[7]));
    g_xh[gn1*8 + (c0>>3)] = make_uint4(f2h2(y1[0],y1[1]), f2h2(y1[2],y1[3]), f2h2(y1[4],y1[5]), f2h2(y1[6],y1[7]));
}

// ---------------- fused conv layer (+ optional fused output head) ----------------
__global__ __launch_bounds__(256, 2) void conv_kernel(
    int dir,
    const float* __restrict__ W, const float* __restrict__ bias,
    const float* __restrict__ gam, const float* __restrict__ bet,
    const float* __restrict__ Wo, const float* __restrict__ bo,
    float* __restrict__ outp)
{
    const float* __restrict__ xin  = dir ? g_y  : g_x;
    const uint4* __restrict__ xinh = dir ? g_yh : g_xh;
    float*       __restrict__ xout = dir ? g_x  : g_y;
    uint4*       __restrict__ xouth= dir ? g_xh : g_yh;

    extern __shared__ float sm[];
    float* sW    = sm;                 // 128*64
    float* scomb = sm + 8192;          // 64*132
    float* sb    = scomb + 8448;
    float* sg    = sb + 64;
    float* sbe   = sg + 64;
    float* sWo   = sbe + 64;           // 64*32
    float* sbo   = sWo + 2048;         // 32

    int t = threadIdx.x;
    #pragma unroll 4
    for (int i = t; i < 8192; i += 256) sW[i] = W[i];
    if (t < 64) { sb[t] = bias[t]; sg[t] = gam[t]; sbe[t] = bet[t]; }
    if (outp) {
        for (int i = t; i < HD*OUTF; i += 256) sWo[i] = Wo[i];
        if (t < OUTF) sbo[t] = bo[t];
    }

    // ---- phase A: self (fp32) + mean-aggregate neighbors (fp16 rows), 4 thr/node
    {
        int node = t >> 2;
        int q = t & 3;
        int gn = blockIdx.x*64 + node;
        int b = gn / NN;
        int start = g_rowptr[gn], end = g_cursor[gn];

        const float4* xr = (const float4*)(xin + (size_t)gn*HD) + q*4;
        float4 s0 = xr[0], s1 = xr[1], s2 = xr[2], s3 = xr[3];
        float* cp = &scomb[node*132 + q*16];
        *(float4*)(cp)    = s0;
        *(float4*)(cp+4)  = s1;
        *(float4*)(cp+8)  = s2;
        *(float4*)(cp+12) = s3;

        const int* csr = g_csr + b*NE;
        const uint4* xh = xinh + (size_t)b*NN*8 + q*2;   // row = 8 uint4
        u64 acc[8] = {0,0,0,0,0,0,0,0};
        int j = start;
        for (; j + 4 <= end; j += 4) {
            int i0 = csr[j], i1 = csr[j+1], i2 = csr[j+2], i3 = csr[j+3];
            uint4 a0 = xh[i0*8],     a1 = xh[i0*8 + 1];
            uint4 b0 = xh[i1*8],     b1 = xh[i1*8 + 1];
            uint4 c0v= xh[i2*8],     c1 = xh[i2*8 + 1];
            uint4 d0 = xh[i3*8],     d1 = xh[i3*8 + 1];
            acc16(acc, a0, a1);
            acc16(acc, b0, b1);
            acc16(acc, c0v, c1);
            acc16(acc, d0, d1);
        }
        for (; j < end; j++) {
            int i0 = csr[j];
            uint4 a0 = xh[i0*8], a1 = xh[i0*8 + 1];
            acc16(acc, a0, a1);
        }
        u64 SC = pk(1.f / fmaxf((float)(end - start), 1.f));
        #pragma unroll
        for (int r = 0; r < 8; r++) mul2(acc[r], SC);
        float* ap = cp + 64;
        *(ulonglong2*)(ap)    = make_ulonglong2(acc[0], acc[1]);
        *(ulonglong2*)(ap+4)  = make_ulonglong2(acc[2], acc[3]);
        *(ulonglong2*)(ap+8)  = make_ulonglong2(acc[4], acc[5]);
        *(ulonglong2*)(ap+12) = make_ulonglong2(acc[6], acc[7]);
    }
    __syncthreads();

    // ---- phase B: y = combined@W (f32x2); epilogue bias+residual+LN+relu
    int colg = t & 7, pair = t >> 3;
    int c0 = colg << 3;
    int n0 = pair*2, n1 = n0 + 1;
    const float* cb0 = &scomb[n0*132];
    const float* cb1 = &scomb[n1*132];

    u64 p0[4] = {0,0,0,0}, p1[4] = {0,0,0,0};
    for (int k = 0; k < 128; k += 4) {
        float4 a0 = *(const float4*)(cb0 + k);
        float4 a1 = *(const float4*)(cb1 + k);
        #pragma unroll
        for (int kk = 0; kk < 4; kk++) {
            u64 A0 = pk(((const float*)&a0)[kk]);
            u64 A1 = pk(((const float*)&a1)[kk]);
            const ulonglong2* wp = (const ulonglong2*)&sW[(k+kk)*HD + c0];
            ulonglong2 wa = wp[0], wb = wp[1];
            fma2(p0[0], A0, wa.x); fma2(p0[1], A0, wa.y); fma2(p0[2], A0, wb.x); fma2(p0[3], A0, wb.y);
            fma2(p1[0], A1, wa.x); fma2(p1[1], A1, wa.y); fma2(p1[2], A1, wb.x); fma2(p1[3], A1, wb.y);
        }
    }

    float y0[8], y1[8];
    #pragma unroll
    for (int j = 0; j < 4; j++) { upk(p0[j], y0[2*j], y0[2*j+1]); upk(p1[j], y1[2*j], y1[2*j+1]); }
    float s0 = 0.f, q0 = 0.f, s1 = 0.f, q1 = 0.f;
    #pragma unroll
    for (int j = 0; j < 8; j++) {
        y0[j] += sb[c0+j] + cb0[c0+j];
        y1[j] += sb[c0+j] + cb1[c0+j];
        s0 += y0[j]; q0 += y0[j]*y0[j];
        s1 += y1[j]; q1 += y1[j]*y1[j];
    }
    #pragma unroll
    for (int off = 1; off < 8; off <<= 1) {
        s0 += __shfl_xor_sync(0xffffffffu, s0, off, 8);
        q0 += __shfl_xor_sync(0xffffffffu, q0, off, 8);
        s1 += __shfl_xor_sync(0xffffffffu, s1, off, 8);
        q1 += __shfl_xor_sync(0xffffffffu, q1, off, 8);
    }
    const float invH = 1.f/64.f;
    float mu0 = s0*invH, var0 = q0*invH - mu0*mu0;
    float mu1 = s1*invH, var1 = q1*invH - mu1*mu1;
    float iv0 = rsqrtf(var0 + LNEPS);
    float iv1 = rsqrtf(var1 + LNEPS);

    float r0[8], r1[8];
    #pragma unroll
    for (int j = 0; j < 8; j++) {
        r0[j] = fmaxf((y0[j]-mu0)*iv0*sg[c0+j] + sbe[c0+j], 0.f);
        r1[j] = fmaxf((y1[j]-mu1)*iv1*sg[c0+j] + sbe[c0+j], 0.f);
    }

    size_t gn0 = (size_t)blockIdx.x*64 + n0, gn1 = gn0 + 1;
    if (!outp) {
        float* o0 = xout + gn0*HD + c0;
        float* o1 = xout + gn1*HD + c0;
        *(float4*)(o0)   = make_float4(r0[0], r0[1], r0[2], r0[3]);
        *(float4*)(o0+4) = make_float4(r0[4], r0[5], r0[6], r0[7]);
        *(float4*)(o1)   = make_float4(r1[0], r1[1], r1[2], r1[3]);
        *(float4*)(o1+4) = make_float4(r1[4], r1[5], r1[6], r1[7]);
        xouth[gn0*8 + (c0>>3)] = make_uint4(f2h2(r0[0],r0[1]), f2h2(r0[2],r0[3]), f2h2(r0[4],r0[5]), f2h2(r0[6],r0[7]));
        xouth[gn1*8 + (c0>>3)] = make_uint4(f2h2(r1[0],r1[1]), f2h2(r1[2],r1[3]), f2h2(r1[4],r1[5]), f2h2(r1[6],r1[7]));
        return;
    }

    // ---- fused output head: out = r @ Wo + bo
    __syncthreads();
    {
        float* w0p = &scomb[n0*132 + c0];
        float* w1p = &scomb[n1*132 + c0];
        *(float4*)(w0p)   = make_float4(r0[0], r0[1], r0[2], r0[3]);
        *(float4*)(w0p+4) = make_float4(r0[4], r0[5], r0[6], r0[7]);
        *(float4*)(w1p)   = make_float4(r1[0], r1[1], r1[2], r1[3]);
        *(float4*)(w1p+4) = make_float4(r1[4], r1[5], r1[6], r1[7]);
    }
    __syncthreads();

    int c4 = colg << 2;
    u64 q0p[2] = {0,0}, q1p[2] = {0,0};
    const float* x0 = &scomb[n0*132];
    const float* x1 = &scomb[n1*132];
    for (int k = 0; k < HD; k += 4) {
        float4 a0 = *(const float4*)(x0 + k);
        float4 a1 = *(const float4*)(x1 + k);
        #pragma unroll
        for (int kk = 0; kk < 4; kk++) {
            u64 A0 = pk(((const float*)&a0)[kk]);
            u64 A1 = pk(((const float*)&a1)[kk]);
            ulonglong2 w = *(const ulonglong2*)&sWo[(k+kk)*OUTF + c4];
            fma2(q0p[0], A0, w.x); fma2(q0p[1], A0, w.y);
            fma2(q1p[0], A1, w.x); fma2(q1p[1], A1, w.y);
        }
    }
    float z0[4], z1[4];
    upk(q0p[0], z0[0], z0[1]); upk(q0p[1], z0[2], z0[3]);
    upk(q1p[0], z1[0], z1[1]); upk(q1p[1], z1[2], z1[3]);
    float4 o0 = make_float4(z0[0]+sbo[c4], z0[1]+sbo[c4+1], z0[2]+sbo[c4+2], z0[3]+sbo[c4+3]);
    float4 o1 = make_float4(z1[0]+sbo[c4], z1[1]+sbo[c4+1], z1[2]+sbo[c4+2], z1[3]+sbo[c4+3]);
    *(float4*)(outp + gn0*OUTF + c4) = o0;
    *(float4*)(outp + gn1*OUTF + c4) = o1;
}

// ---------------- launch ----------------
extern "C" void kernel_launch(void* const* d_in, const int* in_sizes, int n_in,
                              void* d_out, int out_size) {
    const float* nf     = (const float*)d_in[0];
    const void*  ei     = d_in[1];
    const float* enc_w1 = (const float*)d_in[3];
    const float* enc_b1 = (const float*)d_in[4];
    const float* enc_w2 = (const float*)d_in[5];
    const float* enc_b2 = (const float*)d_in[6];
    const float* conv_w = (const float*)d_in[7];
    const float* conv_b = (const float*)d_in[8];
    const float* ln_g   = (const float*)d_in[9];
    const float* ln_b   = (const float*)d_in[10];
    const float* out_w  = (const float*)d_in[11];
    const float* out_b  = (const float*)d_in[12];
    float* out = (float*)d_out;

    detect_zero_kernel<<<(BN + 255)/256, 256>>>((const int*)ei);
    int eb = (BATCH*NE + 255)/256;
    hist_kernel<<<eb, 256>>>(ei);
    scan_kernel<<<BATCH, 1024>>>();
    scatter_kernel<<<eb, 256>>>(ei);

    encode_kernel<<<BN/64, 256>>>(nf, enc_w1, enc_b1, enc_w2, enc_b2);

    int convsmem = (8192 + 8448 + 192 + 2048 + 32) * (int)sizeof(float);   // 75648 B
    cudaFuncSetAttribute(conv_kernel, cudaFuncAttributeMaxDynamicSharedMemorySize, convsmem);
    for (int l = 0; l < 3; l++) {
        conv_kernel<<<BN/64, 256, convsmem>>>(l & 1,
            conv_w + (size_t)l*128*64, conv_b + (size_t)l*64,
            ln_g + (size_t)l*64, ln_b + (size_t)l*64,
            out_w, out_b, (l == 2) ? out : nullptr);
    }
}

// round 6
// speedup vs baseline: 1.1864x; 1.0081x over previous
#include <cuda_runtime.h>
#include <cuda_fp16.h>

#define BATCH 16
#define NN    10000
#define NE    160000
#define INF   19
#define HD    64
#define OUTF  32
#define BN    (BATCH*NN)
#define LNEPS 1e-5f

typedef unsigned long long u64;

// ---------------- scratch (device globals; no allocs allowed) ----------------
__device__ float g_x[(size_t)BN*HD];          // ping (fp32)
__device__ float g_y[(size_t)BN*HD];          // pong (fp32)
__device__ uint4 g_xh[(size_t)BN*8];          // ping (fp16 mirror, 128B/row)
__device__ uint4 g_yh[(size_t)BN*8];          // pong (fp16 mirror)
__device__ __align__(16) int g_cnt[BN];
__device__ __align__(16) int g_rowptr[BN];
__device__ __align__(16) int g_cursor[BN];
__device__ int   g_csr[(size_t)BATCH*NE];
__device__ int   g_is64;

// ---------------- packed f32x2 helpers ----------------
__device__ __forceinline__ u64 pk(float x) {
    u64 r; asm("mov.b64 %0,{%1,%1};" : "=l"(r) : "f"(x)); return r;
}
__device__ __forceinline__ void fma2(u64& d, u64 a, u64 b) {
    asm("fma.rn.f32x2 %0,%1,%2,%0;" : "+l"(d) : "l"(a), "l"(b));
}
__device__ __forceinline__ void add2(u64& d, u64 a) {
    asm("add.rn.f32x2 %0,%0,%1;" : "+l"(d) : "l"(a));
}
__device__ __forceinline__ void mul2(u64& d, u64 a) {
    asm("mul.rn.f32x2 %0,%0,%1;" : "+l"(d) : "l"(a));
}
__device__ __forceinline__ void upk(u64 v, float& lo, float& hi) {
    asm("mov.b64 {%0,%1},%2;" : "=f"(lo), "=f"(hi) : "l"(v));
}
// half2 (as u32) -> f32x2 accumulate
__device__ __forceinline__ void addh2(u64& acc, unsigned h) {
    __half2 hh = *(__half2*)&h;
    float2 f = __half22float2(hh);
    u64 p; asm("mov.b64 %0,{%1,%2};" : "=l"(p) : "f"(f.x), "f"(f.y));
    add2(acc, p);
}
__device__ __forceinline__ void acc16(u64* acc, uint4 A, uint4 B) {
    addh2(acc[0], A.x); addh2(acc[1], A.y); addh2(acc[2], A.z); addh2(acc[3], A.w);
    addh2(acc[4], B.x); addh2(acc[5], B.y); addh2(acc[6], B.z); addh2(acc[7], B.w);
}
__device__ __forceinline__ unsigned f2h2(float a, float b) {
    __half2 h = __floats2half2_rn(a, b);
    return *(unsigned*)&h;
}
// packed fp16 add on uint4 (4x HADD2)
__device__ __forceinline__ uint4 h4add(uint4 a, uint4 b) {
    uint4 r;
    __half2 x, y;
    x = *(__half2*)&a.x; y = *(__half2*)&b.x; x = __hadd2(x, y); r.x = *(unsigned*)&x;
    x = *(__half2*)&a.y; y = *(__half2*)&b.y; x = __hadd2(x, y); r.y = *(unsigned*)&x;
    x = *(__half2*)&a.z; y = *(__half2*)&b.z; x = __hadd2(x, y); r.z = *(unsigned*)&x;
    x = *(__half2*)&a.w; y = *(__half2*)&b.w; x = __hadd2(x, y); r.w = *(unsigned*)&x;
    return r;
}

// ---------------- detect (block0 warp0) + zero counters, fused ----------------
__global__ void detect_zero_kernel(const int* __restrict__ e) {
    int i = blockIdx.x*256 + threadIdx.x;
    if (i < BN) g_cnt[i] = 0;
    if (blockIdx.x == 0 && threadIdx.x < 32) {
        int nz = 0;
        #pragma unroll
        for (int k = threadIdx.x; k < 128; k += 32) nz |= e[2*k + 1];
        unsigned any = __ballot_sync(0xffffffffu, nz != 0);
        if (threadIdx.x == 0) g_is64 = (any == 0) ? 1 : 0;
    }
}

// ---------------- hist: 4 edges per thread (vector loads, MLP) ----------------
__global__ __launch_bounds__(256) void hist_kernel(const void* __restrict__ ei) {
    int i = blockIdx.x*256 + threadIdx.x;
    if (i >= BATCH*NE/4) return;
    int is64 = g_is64;
    int i4 = i*4;
    int b = i4 / NE, e = i4 - b*NE;
    int d0, d1, d2, d3;
    if (is64) {
        const longlong2* p = (const longlong2*)((const long long*)ei + (size_t)b*2*NE + NE + e);
        longlong2 v0 = p[0], v1 = p[1];
        d0 = (int)v0.x; d1 = (int)v0.y; d2 = (int)v1.x; d3 = (int)v1.y;
    } else {
        int4 v = *(const int4*)((const int*)ei + (size_t)b*2*NE + NE + e);
        d0 = v.x; d1 = v.y; d2 = v.z; d3 = v.w;
    }
    int* cb = g_cnt + b*NN;
    atomicAdd(cb + d0, 1); atomicAdd(cb + d1, 1);
    atomicAdd(cb + d2, 1); atomicAdd(cb + d3, 1);
}

// int4 scan: 2500 int4 per batch, 3 chunks of 1024, register carry
__global__ void scan_kernel() {
    __shared__ int wsum[32];
    int b = blockIdx.x, t = threadIdx.x, lane = t & 31, w = t >> 5;
    const int4* c4 = (const int4*)(g_cnt + b*NN);
    int4* r4 = (int4*)(g_rowptr + b*NN);
    int4* u4 = (int4*)(g_cursor + b*NN);
    int carry = 0;
    for (int base = 0; base < 2500; base += 1024) {
        int i = base + t;
        int4 v = (i < 2500) ? c4[i] : make_int4(0,0,0,0);
        int t1 = v.x, t2 = t1 + v.y, t3 = t2 + v.z, t4 = t3 + v.w;
        int x = t4;
        #pragma unroll
        for (int o = 1; o < 32; o <<= 1) {
            int y = __shfl_up_sync(0xffffffffu, x, o);
            if (lane >= o) x += y;
        }
        if (lane == 31) wsum[w] = x;
        __syncthreads();
        if (w == 0) {
            int s = wsum[lane];
            #pragma unroll
            for (int o = 1; o < 32; o <<= 1) {
                int y = __shfl_up_sync(0xffffffffu, s, o);
                if (lane >= o) s += y;
            }
            wsum[lane] = s;
        }
        __syncthreads();
        int excl = carry + (w ? wsum[w-1] : 0) + x - t4;
        if (i < 2500) {
            int4 rp = make_int4(excl, excl + t1, excl + t2, excl + t3);
            r4[i] = rp; u4[i] = rp;
        }
        carry += wsum[31];
        __syncthreads();
    }
}

// ---------------- scatter: 4 edges per thread ----------------
__global__ __launch_bounds__(256) void scatter_kernel(const void* __restrict__ ei) {
    int i = blockIdx.x*256 + threadIdx.x;
    if (i >= BATCH*NE/4) return;
    int is64 = g_is64;
    int i4 = i*4;
    int b = i4 / NE, e = i4 - b*NE;
    int s0, s1, s2, s3, d0, d1, d2, d3;
    if (is64) {
        const longlong2* ps = (const longlong2*)((const long long*)ei + (size_t)b*2*NE + e);
        const longlong2* pd = (const longlong2*)((const long long*)ei + (size_t)b*2*NE + NE + e);
        longlong2 sv0 = ps[0], sv1 = ps[1], dv0 = pd[0], dv1 = pd[1];
        s0 = (int)sv0.x; s1 = (int)sv0.y; s2 = (int)sv1.x; s3 = (int)sv1.y;
        d0 = (int)dv0.x; d1 = (int)dv0.y; d2 = (int)dv1.x; d3 = (int)dv1.y;
    } else {
        int4 sv = *(const int4*)((const int*)ei + (size_t)b*2*NE + e);
        int4 dv = *(const int4*)((const int*)ei + (size_t)b*2*NE + NE + e);
        s0 = sv.x; s1 = sv.y; s2 = sv.z; s3 = sv.w;
        d0 = dv.x; d1 = dv.y; d2 = dv.z; d3 = dv.w;
    }
    int* cur = g_cursor + b*NN;
    int* csr = g_csr + b*NE;
    csr[atomicAdd(cur + d0, 1)] = s0;
    csr[atomicAdd(cur + d1, 1)] = s1;
    csr[atomicAdd(cur + d2, 1)] = s2;
    csr[atomicAdd(cur + d3, 1)] = s3;
}

// ---------------- encoder: x = relu(nf@W1+b1)@W2+b2; writes fp32 + fp16 mirror ----------------
__global__ __launch_bounds__(256) void encode_kernel(
    const float* __restrict__ nf,
    const float* __restrict__ W1, const float* __restrict__ b1,
    const float* __restrict__ W2, const float* __restrict__ b2)
{
    __shared__ float sW1[INF*HD];
    __shared__ float sW2[HD*HD];
    __shared__ float sb1[HD], sb2[HD];
    __shared__ float snf[64*20];
    __shared__ float sh[64*68];
    int t = threadIdx.x;
    for (int i = t; i < INF*HD; i += 256) sW1[i] = W1[i];
    for (int i = t; i < HD*HD;  i += 256) sW2[i] = W2[i];
    if (t < HD) { sb1[t] = b1[t]; sb2[t] = b2[t]; }
    int base = blockIdx.x * 64;
    for (int i = t; i < 64*INF; i += 256) {
        int node = i / INF, k = i - node*INF;
        snf[node*20 + k] = nf[(size_t)(base + node)*INF + k];
    }
    __syncthreads();

    int colg = t & 7, pair = t >> 3;
    int c0 = colg << 3;
    int n0 = pair*2, n1 = n0 + 1;

    u64 p0[4] = {0,0,0,0}, p1[4] = {0,0,0,0};
    for (int k = 0; k < INF; k++) {
        u64 A0 = pk(snf[n0*20 + k]), A1 = pk(snf[n1*20 + k]);
        const ulonglong2* wp = (const ulonglong2*)&sW1[k*HD + c0];
        ulonglong2 wa = wp[0], wb = wp[1];
        fma2(p0[0], A0, wa.x); fma2(p0[1], A0, wa.y); fma2(p0[2], A0, wb.x); fma2(p0[3], A0, wb.y);
        fma2(p1[0], A1, wa.x); fma2(p1[1], A1, wa.y); fma2(p1[2], A1, wb.x); fma2(p1[3], A1, wb.y);
    }
    float h0[8], h1[8];
    #pragma unroll
    for (int j = 0; j < 4; j++) { upk(p0[j], h0[2*j], h0[2*j+1]); upk(p1[j], h1[2*j], h1[2*j+1]); }
    #pragma unroll
    for (int j = 0; j < 8; j++) {
        sh[n0*68 + c0 + j] = fmaxf(h0[j] + sb1[c0+j], 0.f);
        sh[n1*68 + c0 + j] = fmaxf(h1[j] + sb1[c0+j], 0.f);
    }
    __syncthreads();

    #pragma unroll
    for (int j = 0; j < 4; j++) { p0[j] = 0; p1[j] = 0; }
    for (int k = 0; k < HD; k += 4) {
        float4 a0 = *(const float4*)&sh[n0*68 + k];
        float4 a1 = *(const float4*)&sh[n1*68 + k];
        #pragma unroll
        for (int kk = 0; kk < 4; kk++) {
            u64 A0 = pk(((const float*)&a0)[kk]);
            u64 A1 = pk(((const float*)&a1)[kk]);
            const ulonglong2* wp = (const ulonglong2*)&sW2[(k+kk)*HD + c0];
            ulonglong2 wa = wp[0], wb = wp[1];
            fma2(p0[0], A0, wa.x); fma2(p0[1], A0, wa.y); fma2(p0[2], A0, wb.x); fma2(p0[3], A0, wb.y);
            fma2(p1[0], A1, wa.x); fma2(p1[1], A1, wa.y); fma2(p1[2], A1, wb.x); fma2(p1[3], A1, wb.y);
        }
    }
    float y0[8], y1[8];
    #pragma unroll
    for (int j = 0; j < 4; j++) { upk(p0[j], y0[2*j], y0[2*j+1]); upk(p1[j], y1[2*j], y1[2*j+1]); }
    #pragma unroll
    for (int j = 0; j < 8; j++) { y0[j] += sb2[c0+j]; y1[j] += sb2[c0+j]; }

    size_t gn0 = base + n0, gn1 = base + n1;
    float* o0 = g_x + gn0*HD + c0;
    float* o1 = g_x + gn1*HD + c0;
    *(float4*)(o0)   = make_float4(y0[0], y0[1], y0[2], y0[3]);
    *(float4*)(o0+4) = make_float4(y0[4], y0[5], y0[6], y0[7]);
    *(float4*)(o1)   = make_float4(y1[0], y1[1], y1[2], y1[3]);
    *(float4*)(o1+4) = make_float4(y1[4], y1[5], y1[6], y1[7]);
    g_xh[gn0*8 + (c0>>3)] = make_uint4(f2h2(y0[0],y0[1]), f2h2(y0[2],y0[3]), f2h2(y0[4],y0[5]), f2h2(y0[6],y0[7]));
    g_xh[gn1*8 + (c0>>3)] = make_uint4(f2h2(y1[0],y1[1]), f2h2(y1[2],y1[3]), f2h2(y1[4],y1[5]), f2h2(y1[6],y1[7]));
}

// ---------------- fused conv layer (+ optional fused output head) ----------------
__global__ __launch_bounds__(256, 2) void conv_kernel(
    int dir,
    const float* __restrict__ W, const float* __restrict__ bias,
    const float* __restrict__ gam, const float* __restrict__ bet,
    const float* __restrict__ Wo, const float* __restrict__ bo,
    float* __restrict__ outp)
{
    const float* __restrict__ xin  = dir ? g_y  : g_x;
    const uint4* __restrict__ xinh = dir ? g_yh : g_xh;
    float*       __restrict__ xout = dir ? g_x  : g_y;
    uint4*       __restrict__ xouth= dir ? g_xh : g_yh;

    extern __shared__ float sm[];
    float* sW    = sm;                 // 128*64
    float* scomb = sm + 8192;          // 64*132
    float* sb    = scomb + 8448;
    float* sg    = sb + 64;
    float* sbe   = sg + 64;
    float* sWo   = sbe + 64;           // 64*32
    float* sbo   = sWo + 2048;         // 32

    int t = threadIdx.x;
    #pragma unroll 4
    for (int i = t; i < 8192; i += 256) sW[i] = W[i];
    if (t < 64) { sb[t] = bias[t]; sg[t] = gam[t]; sbe[t] = bet[t]; }
    if (outp) {
        for (int i = t; i < HD*OUTF; i += 256) sWo[i] = Wo[i];
        if (t < OUTF) sbo[t] = bo[t];
    }

    // ---- phase A: self (fp32) + mean-aggregate (fp16 tree-4 + fp32 acc), 4 thr/node
    {
        int node = t >> 2;
        int q = t & 3;
        int gn = blockIdx.x*64 + node;
        int b = gn / NN;
        int start = g_rowptr[gn], end = g_cursor[gn];

        const float4* xr = (const float4*)(xin + (size_t)gn*HD) + q*4;
        float4 s0 = xr[0], s1 = xr[1], s2 = xr[2], s3 = xr[3];
        float* cp = &scomb[node*132 + q*16];
        *(float4*)(cp)    = s0;
        *(float4*)(cp+4)  = s1;
        *(float4*)(cp+8)  = s2;
        *(float4*)(cp+12) = s3;

        const int* csr = g_csr + b*NE;
        const uint4* xh = xinh + (size_t)b*NN*8 + q*2;   // row = 8 uint4
        u64 acc[8] = {0,0,0,0,0,0,0,0};
        int j = start;
        for (; j + 4 <= end; j += 4) {
            int i0 = csr[j], i1 = csr[j+1], i2 = csr[j+2], i3 = csr[j+3];
            uint4 a0 = xh[i0*8], a1 = xh[i0*8 + 1];
            uint4 b0 = xh[i1*8], b1 = xh[i1*8 + 1];
            uint4 c0v= xh[i2*8], c1 = xh[i2*8 + 1];
            uint4 d0 = xh[i3*8], d1 = xh[i3*8 + 1];
            uint4 t0 = h4add(h4add(a0, b0), h4add(c0v, d0));   // depth-2 fp16 tree
            uint4 t1 = h4add(h4add(a1, b1), h4add(c1, d1));
            acc16(acc, t0, t1);                                 // fp32 accumulate
        }
        if (j + 2 <= end) {
            int i0 = csr[j], i1 = csr[j+1];
            uint4 a0 = xh[i0*8], a1 = xh[i0*8 + 1];
            uint4 b0 = xh[i1*8], b1 = xh[i1*8 + 1];
            acc16(acc, h4add(a0, b0), h4add(a1, b1));
            j += 2;
        }
        if (j < end) {
            int i0 = csr[j];
            acc16(acc, xh[i0*8], xh[i0*8 + 1]);
        }
        u64 SC = pk(1.f / fmaxf((float)(end - start), 1.f));
        #pragma unroll
        for (int r = 0; r < 8; r++) mul2(acc[r], SC);
        float* ap = cp + 64;
        *(ulonglong2*)(ap)    = make_ulonglong2(acc[0], acc[1]);
        *(ulonglong2*)(ap+4)  = make_ulonglong2(acc[2], acc[3]);
        *(ulonglong2*)(ap+8)  = make_ulonglong2(acc[4], acc[5]);
        *(ulonglong2*)(ap+12) = make_ulonglong2(acc[6], acc[7]);
    }
    __syncthreads();

    // ---- phase B: y = combined@W (f32x2); epilogue bias+residual+LN+relu
    int colg = t & 7, pair = t >> 3;
    int c0 = colg << 3;
    int n0 = pair*2, n1 = n0 + 1;
    const float* cb0 = &scomb[n0*132];
    const float* cb1 = &scomb[n1*132];

    u64 p0[4] = {0,0,0,0}, p1[4] = {0,0,0,0};
    for (int k = 0; k < 128; k += 4) {
        float4 a0 = *(const float4*)(cb0 + k);
        float4 a1 = *(const float4*)(cb1 + k);
        #pragma unroll
        for (int kk = 0; kk < 4; kk++) {
            u64 A0 = pk(((const float*)&a0)[kk]);
            u64 A1 = pk(((const float*)&a1)[kk]);
            const ulonglong2* wp = (const ulonglong2*)&sW[(k+kk)*HD + c0];
            ulonglong2 wa = wp[0], wb = wp[1];
            fma2(p0[0], A0, wa.x); fma2(p0[1], A0, wa.y); fma2(p0[2], A0, wb.x); fma2(p0[3], A0, wb.y);
            fma2(p1[0], A1, wa.x); fma2(p1[1], A1, wa.y); fma2(p1[2], A1, wb.x); fma2(p1[3], A1, wb.y);
        }
    }

    float y0[8], y1[8];
    #pragma unroll
    for (int j = 0; j < 4; j++) { upk(p0[j], y0[2*j], y0[2*j+1]); upk(p1[j], y1[2*j], y1[2*j+1]); }
    float s0 = 0.f, q0 = 0.f, s1 = 0.f, q1 = 0.f;
    #pragma unroll
    for (int j = 0; j < 8; j++) {
        y0[j] += sb[c0+j] + cb0[c0+j];
        y1[j] += sb[c0+j] + cb1[c0+j];
        s0 += y0[j]; q0 += y0[j]*y0[j];
        s1 += y1[j]; q1 += y1[j]*y1[j];
    }
    #pragma unroll
    for (int off = 1; off < 8; off <<= 1) {
        s0 += __shfl_xor_sync(0xffffffffu, s0, off, 8);
        q0 += __shfl_xor_sync(0xffffffffu, q0, off, 8);
        s1 += __shfl_xor_sync(0xffffffffu, s1, off, 8);
        q1 += __shfl_xor_sync(0xffffffffu, q1, off, 8);
    }
    const float invH = 1.f/64.f;
    float mu0 = s0*invH, var0 = q0*invH - mu0*mu0;
    float mu1 = s1*invH, var1 = q1*invH - mu1*mu1;
    float iv0 = rsqrtf(var0 + LNEPS);
    float iv1 = rsqrtf(var1 + LNEPS);

    float r0[8], r1[8];
    #pragma unroll
    for (int j = 0; j < 8; j++) {
        r0[j] = fmaxf((y0[j]-mu0)*iv0*sg[c0+j] + sbe[c0+j], 0.f);
        r1[j] = fmaxf((y1[j]-mu1)*iv1*sg[c0+j] + sbe[c0+j], 0.f);
    }

    size_t gn0 = (size_t)blockIdx.x*64 + n0, gn1 = gn0 + 1;
    if (!outp) {
        float* o0 = xout + gn0*HD + c0;
        float* o1 = xout + gn1*HD + c0;
        *(float4*)(o0)   = make_float4(r0[0], r0[1], r0[2], r0[3]);
        *(float4*)(o0+4) = make_float4(r0[4], r0[5], r0[6], r0[7]);
        *(float4*)(o1)   = make_float4(r1[0], r1[1], r1[2], r1[3]);
        *(float4*)(o1+4) = make_float4(r1[4], r1[5], r1[6], r1[7]);
        xouth[gn0*8 + (c0>>3)] = make_uint4(f2h2(r0[0],r0[1]), f2h2(r0[2],r0[3]), f2h2(r0[4],r0[5]), f2h2(r0[6],r0[7]));
        xouth[gn1*8 + (c0>>3)] = make_uint4(f2h2(r1[0],r1[1]), f2h2(r1[2],r1[3]), f2h2(r1[4],r1[5]), f2h2(r1[6],r1[7]));
        return;
    }

    // ---- fused output head: out = r @ Wo + bo
    __syncthreads();
    {
        float* w0p = &scomb[n0*132 + c0];
        float* w1p = &scomb[n1*132 + c0];
        *(float4*)(w0p)   = make_float4(r0[0], r0[1], r0[2], r0[3]);
        *(float4*)(w0p+4) = make_float4(r0[4], r0[5], r0[6], r0[7]);
        *(float4*)(w1p)   = make_float4(r1[0], r1[1], r1[2], r1[3]);
        *(float4*)(w1p+4) = make_float4(r1[4], r1[5], r1[6], r1[7]);
    }
    __syncthreads();

    int c4 = colg << 2;
    u64 q0p[2] = {0,0}, q1p[2] = {0,0};
    const float* x0 = &scomb[n0*132];
    const float* x1 = &scomb[n1*132];
    for (int k = 0; k < HD; k += 4) {
        float4 a0 = *(const float4*)(x0 + k);
        float4 a1 = *(const float4*)(x1 + k);
        #pragma unroll
        for (int kk = 0; kk < 4; kk++) {
            u64 A0 = pk(((const float*)&a0)[kk]);
            u64 A1 = pk(((const float*)&a1)[kk]);
            ulonglong2 w = *(const ulonglong2*)&sWo[(k+kk)*OUTF + c4];
            fma2(q0p[0], A0, w.x); fma2(q0p[1], A0, w.y);
            fma2(q1p[0], A1, w.x); fma2(q1p[1], A1, w.y);
        }
    }
    float z0[4], z1[4];
    upk(q0p[0], z0[0], z0[1]); upk(q0p[1], z0[2], z0[3]);
    upk(q1p[0], z1[0], z1[1]); upk(q1p[1], z1[2], z1[3]);
    float4 o0 = make_float4(z0[0]+sbo[c4], z0[1]+sbo[c4+1], z0[2]+sbo[c4+2], z0[3]+sbo[c4+3]);
    float4 o1 = make_float4(z1[0]+sbo[c4], z1[1]+sbo[c4+1], z1[2]+sbo[c4+2], z1[3]+sbo[c4+3]);
    *(float4*)(outp + gn0*OUTF + c4) = o0;
    *(float4*)(outp + gn1*OUTF + c4) = o1;
}

// ---------------- launch ----------------
extern "C" void kernel_launch(void* const* d_in, const int* in_sizes, int n_in,
                              void* d_out, int out_size) {
    const float* nf     = (const float*)d_in[0];
    const void*  ei     = d_in[1];
    const float* enc_w1 = (const float*)d_in[3];
    const float* enc_b1 = (const float*)d_in[4];
    const float* enc_w2 = (const float*)d_in[5];
    const float* enc_b2 = (const float*)d_in[6];
    const float* conv_w = (const float*)d_in[7];
    const float* conv_b = (const float*)d_in[8];
    const float* ln_g   = (const float*)d_in[9];
    const float* ln_b   = (const float*)d_in[10];
    const float* out_w  = (const float*)d_in[11];
    const float* out_b  = (const float*)d_in[12];
    float* out = (float*)d_out;

    detect_zero_kernel<<<(BN + 255)/256, 256>>>((const int*)ei);
    int eb4 = (BATCH*NE/4 + 255)/256;
    hist_kernel<<<eb4, 256>>>(ei);
    scan_kernel<<<BATCH, 1024>>>();
    scatter_kernel<<<eb4, 256>>>(ei);

    encode_kernel<<<BN/64, 256>>>(nf, enc_w1, enc_b1, enc_w2, enc_b2);

    int convsmem = (8192 + 8448 + 192 + 2048 + 32) * (int)sizeof(float);   // 75648 B
    cudaFuncSetAttribute(conv_kernel, cudaFuncAttributeMaxDynamicSharedMemorySize, convsmem);
    for (int l = 0; l < 3; l++) {
        conv_kernel<<<BN/64, 256, convsmem>>>(l & 1,
            conv_w + (size_t)l*128*64, conv_b + (size_t)l*64,
            ln_g + (size_t)l*64, ln_b + (size_t)l*64,
            out_w, out_b, (l == 2) ? out : nullptr);
    }
}